// round 11
// baseline (speedup 1.0000x reference)
#include <cuda_runtime.h>

#define Nn 8192
#define Cc 100
#define Dd 128
#define Hh 128
#define Oo 64
#define TPC 64                 // tokens per CTA chunk
#define NPAIR (TPC / 2)        // 32 token pairs
#define XSTRIDE 260            // words per pair-row (1040 B: 16B-aligned, bank-spread)
#define MAXW 228
#define NB 16
#define BT 512

// ---------------- packed f32x2 helpers ----------------
#define FMA2(d, a, b) asm("fma.rn.f32x2 %0, %1, %2, %0;" : "+l"(d) : "l"(a), "l"(b))
#define DUP2(d, s)    asm("mov.b64 %0, {%1, %1};" : "=l"(d) : "f"(s))
#define PK2(d, lo, hi) asm("mov.b64 %0, {%1, %2};" : "=l"(d) : "f"(lo), "f"(hi))
#define UNPK2(lo, hi, s) asm("mov.b64 {%0, %1}, %2;" : "=f"(lo), "=f"(hi) : "l"(s))
#define CP_ASYNC16(smem_u32, gptr) \
    asm volatile("cp.async.cg.shared.global [%0], [%1], 16;" :: "r"(smem_u32), "l"(gptr))
#define CP_ASYNC_COMMIT() asm volatile("cp.async.commit_group;")
#define CP_ASYNC_WAIT0()  asm volatile("cp.async.wait_group 0;")

// ---------------- scratch (no allocations allowed) ----------------
__device__ int g_perm[Nn];
__device__ int g_workCat[MAXW];
__device__ int g_workStart[MAXW];
__device__ int g_workCnt[MAXW];
__device__ int g_numWork;

// ---------------- single-launch counting sort ----------------
__global__ void __launch_bounds__(BT) k_sort(const int* __restrict__ cat) {
    __shared__ int h_tot[128];
    __shared__ int h_pre[128];
    __shared__ int s_scan[128];
    int t = threadIdx.x, b = blockIdx.x;
    if (t < 128) { h_tot[t] = 0; h_pre[t] = 0; }
    __syncthreads();

    int myseg = b * BT;
    #pragma unroll 4
    for (int i = t; i < Nn; i += BT) {
        int c = cat[i];
        atomicAdd(&h_tot[c], 1);
        if (i < myseg) atomicAdd(&h_pre[c], 1);
    }
    __syncthreads();

    int p_mine = 0;
    if (t < 128) {
        int tot = (t < Cc) ? h_tot[t] : 0;
        p_mine = tot | (((tot + TPC - 1) / TPC) << 16);
        s_scan[t] = p_mine;
    }
    __syncthreads();
    #pragma unroll
    for (int d = 1; d < 128; d <<= 1) {
        int v = 0;
        if (t < 128 && t >= d) v = s_scan[t - d];
        __syncthreads();
        if (t < 128) s_scan[t] += v;
        __syncthreads();
    }

    if (t < Cc) {
        int excl = s_scan[t] - p_mine;
        int offEx = excl & 0xFFFF;
        h_pre[t] += offEx;
        if (b == 0) {
            int coffEx = excl >> 16;
            int tot = p_mine & 0xFFFF;
            int nch = p_mine >> 16;
            for (int j = 0; j < nch; j++) {
                g_workCat[coffEx + j]   = t;
                g_workStart[coffEx + j] = offEx + j * TPC;
                int rem = tot - j * TPC;
                g_workCnt[coffEx + j]   = rem < TPC ? rem : TPC;
            }
        }
    }
    if (b == 0 && t == 127) g_numWork = s_scan[127] >> 16;
    __syncthreads();

    int id = myseg + t;
    int pos = atomicAdd(&h_pre[cat[id]], 1);
    g_perm[pos] = id;
}

// ---------------- main fused MLP (TPC=64, W2 reuses W1 buffer) ----------------
// SMEM = Wbuf 64KB (W1 phase1, W2 phase2) + xp 32.5KB = 96.5KB -> 2 CTAs/SM.
// Layer 1: warp = 16 pairs x 32 cols; lane = 4 pairs x 4 cols (P=4,C=4: 5.33 FMA2/wf).
// Layer 2: warp = 16 pairs x 16 cols; lane = 2 pairs x 4 cols.
__global__ void __launch_bounds__(256, 2)
k_mlp(const float* __restrict__ x,
      const float* __restrict__ W1, const float* __restrict__ b1,
      const float* __restrict__ W2, const float* __restrict__ b2,
      float* __restrict__ out) {
    extern __shared__ float sm[];
    float* Wbuf = sm;                     // 16384 f : W1 [d][h], later W2 [k][o]
    float* xp   = sm + Dd * Hh;           // 32*260 f : pair-major packed x / h

    int w = blockIdx.x;
    if (w >= g_numWork) return;
    int c     = g_workCat[w];
    int start = g_workStart[w];
    int cnt   = g_workCnt[w];
    int t = threadIdx.x;

    unsigned wba = (unsigned)__cvta_generic_to_shared(Wbuf);

    // ---- stage W1 via cp.async (overlaps x gather) ----
    {
        const float4* W1g = (const float4*)(W1 + (size_t)c * Dd * Hh);
        #pragma unroll
        for (int i = t; i < Dd * Hh / 4; i += 256)
            CP_ASYNC16(wba + i * 16, W1g + i);
        CP_ASYNC_COMMIT();
    }

    // ---- stage x transposed+pair-packed: xp[p][d] = (x_{2p}[d], x_{2p+1}[d]) ----
    #pragma unroll
    for (int i = t; i < NPAIR * 32; i += 256) {
        int p = i >> 5, q = i & 31;            // q indexes d-quads
        int iA = 2 * p, iB = 2 * p + 1;
        int tA = (iA < cnt) ? g_perm[start + iA] : -1;
        int tB = (iB < cnt) ? g_perm[start + iB] : -1;
        float4 a = (tA >= 0) ? ((const float4*)(x + (size_t)tA * Dd))[q]
                             : make_float4(0.f, 0.f, 0.f, 0.f);
        float4 bb = (tB >= 0) ? ((const float4*)(x + (size_t)tB * Dd))[q]
                              : make_float4(0.f, 0.f, 0.f, 0.f);
        float* dst = xp + (size_t)p * XSTRIDE + 8 * q;
        ((float4*)dst)[0] = make_float4(a.x, bb.x, a.y, bb.y);
        ((float4*)dst)[1] = make_float4(a.z, bb.z, a.w, bb.w);
    }
    CP_ASYNC_WAIT0();
    __syncthreads();

    int warp = t >> 5, lane = t & 31;

    // ================= layer 1 =================
    int pg = warp & 1;                     // pair half (16 pairs)
    int cg = warp >> 1;                    // col group (32 cols)
    int rb = 16 * pg + (lane & 3);         // lane's rows: rb + 4k, k=0..3 (bank-spread)
    int cbase = 32 * cg + 4 * (lane >> 2); // lane's 4 H-cols

    unsigned long long acc[4][4];
    #pragma unroll
    for (int k = 0; k < 4; k++)
        #pragma unroll
        for (int j = 0; j < 4; j++) acc[k][j] = 0ULL;

    if (32 * pg < cnt) {
        const float* xr0 = xp + (size_t)(rb + 0) * XSTRIDE;
        const float* xr1 = xp + (size_t)(rb + 4) * XSTRIDE;
        const float* xr2 = xp + (size_t)(rb + 8) * XSTRIDE;
        const float* xr3 = xp + (size_t)(rb + 12) * XSTRIDE;
        const float* Wr  = Wbuf + cbase;
        ulonglong2 xv0 = *(const ulonglong2*)(xr0);
        ulonglong2 xv1 = *(const ulonglong2*)(xr1);
        ulonglong2 xv2 = *(const ulonglong2*)(xr2);
        ulonglong2 xv3 = *(const ulonglong2*)(xr3);
        float4 wa = *(const float4*)(Wr);
        float4 wb = *(const float4*)(Wr + Hh);
        #pragma unroll 2
        for (int d = 0; d < Dd; d += 2) {
            ulonglong2 nx0, nx1, nx2, nx3;
            float4 nwa, nwb;
            if (d + 2 < Dd) {
                nx0 = *(const ulonglong2*)(xr0 + 2 * (d + 2));
                nx1 = *(const ulonglong2*)(xr1 + 2 * (d + 2));
                nx2 = *(const ulonglong2*)(xr2 + 2 * (d + 2));
                nx3 = *(const ulonglong2*)(xr3 + 2 * (d + 2));
                nwa = *(const float4*)(Wr + (size_t)(d + 2) * Hh);
                nwb = *(const float4*)(Wr + (size_t)(d + 3) * Hh);
            }
            unsigned long long a0, a1, a2w, a3, b0, b1, b2w, b3;
            DUP2(a0, wa.x); DUP2(a1, wa.y); DUP2(a2w, wa.z); DUP2(a3, wa.w);
            DUP2(b0, wb.x); DUP2(b1, wb.y); DUP2(b2w, wb.z); DUP2(b3, wb.w);
            FMA2(acc[0][0], xv0.x, a0); FMA2(acc[0][1], xv0.x, a1);
            FMA2(acc[0][2], xv0.x, a2w); FMA2(acc[0][3], xv0.x, a3);
            FMA2(acc[1][0], xv1.x, a0); FMA2(acc[1][1], xv1.x, a1);
            FMA2(acc[1][2], xv1.x, a2w); FMA2(acc[1][3], xv1.x, a3);
            FMA2(acc[2][0], xv2.x, a0); FMA2(acc[2][1], xv2.x, a1);
            FMA2(acc[2][2], xv2.x, a2w); FMA2(acc[2][3], xv2.x, a3);
            FMA2(acc[3][0], xv3.x, a0); FMA2(acc[3][1], xv3.x, a1);
            FMA2(acc[3][2], xv3.x, a2w); FMA2(acc[3][3], xv3.x, a3);
            FMA2(acc[0][0], xv0.y, b0); FMA2(acc[0][1], xv0.y, b1);
            FMA2(acc[0][2], xv0.y, b2w); FMA2(acc[0][3], xv0.y, b3);
            FMA2(acc[1][0], xv1.y, b0); FMA2(acc[1][1], xv1.y, b1);
            FMA2(acc[1][2], xv1.y, b2w); FMA2(acc[1][3], xv1.y, b3);
            FMA2(acc[2][0], xv2.y, b0); FMA2(acc[2][1], xv2.y, b1);
            FMA2(acc[2][2], xv2.y, b2w); FMA2(acc[2][3], xv2.y, b3);
            FMA2(acc[3][0], xv3.y, b0); FMA2(acc[3][1], xv3.y, b1);
            FMA2(acc[3][2], xv3.y, b2w); FMA2(acc[3][3], xv3.y, b3);
            xv0 = nx0; xv1 = nx1; xv2 = nx2; xv3 = nx3; wa = nwa; wb = nwb;
        }
    }

    __syncthreads();   // all reads of W1 and xp complete

    // ---- stage W2 into Wbuf (reuse) — overlaps epilogue 1 ----
    {
        const float4* W2g = (const float4*)(W2 + (size_t)c * Hh * Oo);
        #pragma unroll
        for (int i = t; i < Hh * Oo / 4; i += 256)
            CP_ASYNC16(wba + i * 16, W2g + i);
        CP_ASYNC_COMMIT();
    }

    // epilogue 1: bias + relu, store pair-packed h in place over xp
    if (32 * pg < cnt) {
        float4 bv = *(const float4*)(b1 + (size_t)c * Hh + cbase);
        float bj[4] = {bv.x, bv.y, bv.z, bv.w};
        #pragma unroll
        for (int k = 0; k < 4; k++) {
            int row = rb + 4 * k;
            ulonglong2 v;
            float l0, h0, l1, h1, l2, h2, l3, h3;
            UNPK2(l0, h0, acc[k][0]);
            UNPK2(l1, h1, acc[k][1]);
            UNPK2(l2, h2, acc[k][2]);
            UNPK2(l3, h3, acc[k][3]);
            l0 = fmaxf(l0 + bj[0], 0.f); h0 = fmaxf(h0 + bj[0], 0.f);
            l1 = fmaxf(l1 + bj[1], 0.f); h1 = fmaxf(h1 + bj[1], 0.f);
            PK2(v.x, l0, h0); PK2(v.y, l1, h1);
            *(ulonglong2*)(xp + (size_t)row * XSTRIDE + 2 * cbase) = v;
            l2 = fmaxf(l2 + bj[2], 0.f); h2 = fmaxf(h2 + bj[2], 0.f);
            l3 = fmaxf(l3 + bj[3], 0.f); h3 = fmaxf(h3 + bj[3], 0.f);
            PK2(v.x, l2, h2); PK2(v.y, l3, h3);
            *(ulonglong2*)(xp + (size_t)row * XSTRIDE + 2 * cbase + 4) = v;
        }
    }
    CP_ASYNC_WAIT0();
    __syncthreads();   // h visible + W2 staged

    // ================= layer 2 =================
    int pg2 = warp & 1;                    // pair half (16 pairs)
    int cg2 = warp >> 1;                   // col group (16 cols)
    int r2 = 16 * pg2 + (lane & 7);        // lane's rows: r2, r2+8 (bank-spread)
    int cb2 = 16 * cg2 + 4 * (lane >> 3);  // lane's 4 O-cols

    if (32 * pg2 < cnt) {
        unsigned long long acc2[2][4];
        #pragma unroll
        for (int k = 0; k < 2; k++)
            #pragma unroll
            for (int j = 0; j < 4; j++) acc2[k][j] = 0ULL;

        const float* hr0 = xp + (size_t)r2 * XSTRIDE;
        const float* hr1 = xp + (size_t)(r2 + 8) * XSTRIDE;
        const float* Wr2 = Wbuf + cb2;
        ulonglong2 h0 = *(const ulonglong2*)(hr0);
        ulonglong2 h1 = *(const ulonglong2*)(hr1);
        float4 wA = *(const float4*)(Wr2);
        float4 wB = *(const float4*)(Wr2 + Oo);
        #pragma unroll 2
        for (int k = 0; k < Hh; k += 2) {
            ulonglong2 nh0, nh1;
            float4 nA, nB;
            if (k + 2 < Hh) {
                nh0 = *(const ulonglong2*)(hr0 + 2 * (k + 2));
                nh1 = *(const ulonglong2*)(hr1 + 2 * (k + 2));
                nA = *(const float4*)(Wr2 + (size_t)(k + 2) * Oo);
                nB = *(const float4*)(Wr2 + (size_t)(k + 3) * Oo);
            }
            unsigned long long wA0, wA1, wA2, wA3, wB0, wB1, wB2, wB3;
            DUP2(wA0, wA.x); DUP2(wA1, wA.y); DUP2(wA2, wA.z); DUP2(wA3, wA.w);
            DUP2(wB0, wB.x); DUP2(wB1, wB.y); DUP2(wB2, wB.z); DUP2(wB3, wB.w);
            FMA2(acc2[0][0], h0.x, wA0); FMA2(acc2[0][1], h0.x, wA1);
            FMA2(acc2[0][2], h0.x, wA2); FMA2(acc2[0][3], h0.x, wA3);
            FMA2(acc2[1][0], h1.x, wA0); FMA2(acc2[1][1], h1.x, wA1);
            FMA2(acc2[1][2], h1.x, wA2); FMA2(acc2[1][3], h1.x, wA3);
            FMA2(acc2[0][0], h0.y, wB0); FMA2(acc2[0][1], h0.y, wB1);
            FMA2(acc2[0][2], h0.y, wB2); FMA2(acc2[0][3], h0.y, wB3);
            FMA2(acc2[1][0], h1.y, wB0); FMA2(acc2[1][1], h1.y, wB1);
            FMA2(acc2[1][2], h1.y, wB2); FMA2(acc2[1][3], h1.y, wB3);
            h0 = nh0; h1 = nh1; wA = nA; wB = nB;
        }

        // epilogue 2: bias + float4 stores per token
        float4 b2v = *(const float4*)(b2 + (size_t)c * Oo + cb2);
        #pragma unroll
        for (int k = 0; k < 2; k++) {
            int pr = r2 + 8 * k;
            int iA = 2 * pr, iB = iA + 1;
            int tA = (iA < cnt) ? g_perm[start + iA] : -1;
            int tB = (iB < cnt) ? g_perm[start + iB] : -1;
            float l0, h0f, l1, h1f, l2, h2f, l3, h3f;
            UNPK2(l0, h0f, acc2[k][0]);
            UNPK2(l1, h1f, acc2[k][1]);
            UNPK2(l2, h2f, acc2[k][2]);
            UNPK2(l3, h3f, acc2[k][3]);
            if (tA >= 0) {
                float4 o = make_float4(l0 + b2v.x, l1 + b2v.y, l2 + b2v.z, l3 + b2v.w);
                *(float4*)(out + (size_t)tA * Oo + cb2) = o;
            }
            if (tB >= 0) {
                float4 o = make_float4(h0f + b2v.x, h1f + b2v.y, h2f + b2v.z, h3f + b2v.w);
                *(float4*)(out + (size_t)tB * Oo + cb2) = o;
            }
        }
    }
}

extern "C" void kernel_launch(void* const* d_in, const int* in_sizes, int n_in,
                              void* d_out, int out_size) {
    const float* x   = (const float*)d_in[0];
    const int*   cat = (const int*)  d_in[1];
    const float* W1  = (const float*)d_in[2];
    const float* b1  = (const float*)d_in[3];
    const float* W2  = (const float*)d_in[4];
    const float* b2  = (const float*)d_in[5];
    float* out = (float*)d_out;

    size_t smem = (size_t)(Dd * Hh + NPAIR * XSTRIDE) * sizeof(float); // 98816 B
    static bool attr_set = false;
    if (!attr_set) {
        cudaFuncSetAttribute(k_mlp, cudaFuncAttributeMaxDynamicSharedMemorySize, (int)smem);
        attr_set = true;
    }

    k_sort<<<NB, BT>>>(cat);
    k_mlp<<<MAXW, 256, smem>>>(x, W1, b1, W2, b2, out);
}

// round 12
// speedup vs baseline: 1.0790x; 1.0790x over previous
#include <cuda_runtime.h>

#define Nn 8192
#define Cc 100
#define Dd 128
#define Hh 128
#define Oo 64
#define TPC 32                 // tokens per CTA chunk
#define NPAIR (TPC / 2)        // 16 token pairs
#define XSTRIDE 260            // words per pair-row (1040 B: 16B-aligned, bank-spread)
#define MAXW 356
#define NB 16
#define BT 512
#define QF 1024                // float4 per 16KB weight quarter

// ---------------- packed f32x2 helpers ----------------
#define FMA2(d, a, b) asm("fma.rn.f32x2 %0, %1, %2, %0;" : "+l"(d) : "l"(a), "l"(b))
#define DUP2(d, s)    asm("mov.b64 %0, {%1, %1};" : "=l"(d) : "f"(s))
#define PK2(d, lo, hi) asm("mov.b64 %0, {%1, %2};" : "=l"(d) : "f"(lo), "f"(hi))
#define UNPK2(lo, hi, s) asm("mov.b64 {%0, %1}, %2;" : "=f"(lo), "=f"(hi) : "l"(s))
#define CP_ASYNC16(smem_u32, gptr) \
    asm volatile("cp.async.cg.shared.global [%0], [%1], 16;" :: "r"(smem_u32), "l"(gptr))
#define CP_ASYNC_COMMIT() asm volatile("cp.async.commit_group;")
#define CP_ASYNC_WAIT0()  asm volatile("cp.async.wait_group 0;")
#define CP_ASYNC_WAIT1()  asm volatile("cp.async.wait_group 1;")

// ---------------- scratch (no allocations allowed) ----------------
__device__ int g_perm[Nn];
__device__ int g_workCat[MAXW];
__device__ int g_workStart[MAXW];
__device__ int g_workCnt[MAXW];
__device__ int g_numWork;

// ---------------- single-launch counting sort ----------------
__global__ void __launch_bounds__(BT) k_sort(const int* __restrict__ cat) {
    __shared__ int h_tot[128];
    __shared__ int h_pre[128];
    __shared__ int s_scan[128];
    int t = threadIdx.x, b = blockIdx.x;
    if (t < 128) { h_tot[t] = 0; h_pre[t] = 0; }
    __syncthreads();

    int myseg = b * BT;
    #pragma unroll 4
    for (int i = t; i < Nn; i += BT) {
        int c = cat[i];
        atomicAdd(&h_tot[c], 1);
        if (i < myseg) atomicAdd(&h_pre[c], 1);
    }
    __syncthreads();

    int p_mine = 0;
    if (t < 128) {
        int tot = (t < Cc) ? h_tot[t] : 0;
        p_mine = tot | (((tot + TPC - 1) / TPC) << 16);
        s_scan[t] = p_mine;
    }
    __syncthreads();
    #pragma unroll
    for (int d = 1; d < 128; d <<= 1) {
        int v = 0;
        if (t < 128 && t >= d) v = s_scan[t - d];
        __syncthreads();
        if (t < 128) s_scan[t] += v;
        __syncthreads();
    }

    if (t < Cc) {
        int excl = s_scan[t] - p_mine;
        int offEx = excl & 0xFFFF;
        h_pre[t] += offEx;
        if (b == 0) {
            int coffEx = excl >> 16;
            int tot = p_mine & 0xFFFF;
            int nch = p_mine >> 16;
            for (int j = 0; j < nch; j++) {
                g_workCat[coffEx + j]   = t;
                g_workStart[coffEx + j] = offEx + j * TPC;
                int rem = tot - j * TPC;
                g_workCnt[coffEx + j]   = rem < TPC ? rem : TPC;
            }
        }
    }
    if (b == 0 && t == 127) g_numWork = s_scan[127] >> 16;
    __syncthreads();

    int id = myseg + t;
    int pos = atomicAdd(&h_pre[cat[id]], 1);
    g_perm[pos] = id;
}

// one layer-1 quarter: 32 d-rows from Wq (pre-offset by cbase), software-pipelined
__device__ __forceinline__ void l1_quarter(
    unsigned long long (*acc)[4], const float* Wq,
    const float* xr0, const float* xr1, int dbase) {
    ulonglong2 xv0 = *(const ulonglong2*)(xr0 + 2 * dbase);
    ulonglong2 xv1 = *(const ulonglong2*)(xr1 + 2 * dbase);
    float4 wa = *(const float4*)(Wq);
    float4 wb = *(const float4*)(Wq + Hh);
    #pragma unroll 4
    for (int dl = 0; dl < 32; dl += 2) {
        ulonglong2 nx0, nx1;
        float4 nwa, nwb;
        if (dl + 2 < 32) {
            nx0 = *(const ulonglong2*)(xr0 + 2 * (dbase + dl + 2));
            nx1 = *(const ulonglong2*)(xr1 + 2 * (dbase + dl + 2));
            nwa = *(const float4*)(Wq + (size_t)(dl + 2) * Hh);
            nwb = *(const float4*)(Wq + (size_t)(dl + 3) * Hh);
        }
        unsigned long long a0, a1, a2w, a3, b0, b1, b2w, b3;
        DUP2(a0, wa.x); DUP2(a1, wa.y); DUP2(a2w, wa.z); DUP2(a3, wa.w);
        DUP2(b0, wb.x); DUP2(b1, wb.y); DUP2(b2w, wb.z); DUP2(b3, wb.w);
        FMA2(acc[0][0], xv0.x, a0); FMA2(acc[0][1], xv0.x, a1);
        FMA2(acc[0][2], xv0.x, a2w); FMA2(acc[0][3], xv0.x, a3);
        FMA2(acc[1][0], xv1.x, a0); FMA2(acc[1][1], xv1.x, a1);
        FMA2(acc[1][2], xv1.x, a2w); FMA2(acc[1][3], xv1.x, a3);
        FMA2(acc[0][0], xv0.y, b0); FMA2(acc[0][1], xv0.y, b1);
        FMA2(acc[0][2], xv0.y, b2w); FMA2(acc[0][3], xv0.y, b3);
        FMA2(acc[1][0], xv1.y, b0); FMA2(acc[1][1], xv1.y, b1);
        FMA2(acc[1][2], xv1.y, b2w); FMA2(acc[1][3], xv1.y, b3);
        xv0 = nx0; xv1 = nx1; wa = nwa; wb = nwb;
    }
}

// one layer-2 half: 64 k-rows from Wh (pre-offset by cb2), software-pipelined
__device__ __forceinline__ void l2_half(
    unsigned long long (*acc2)[2], const float* Wh,
    const float* hr0, const float* hr1, int kbase) {
    ulonglong2 h0 = *(const ulonglong2*)(hr0 + 2 * kbase);
    ulonglong2 h1 = *(const ulonglong2*)(hr1 + 2 * kbase);
    float2 wA = *(const float2*)(Wh);
    float2 wB = *(const float2*)(Wh + Oo);
    #pragma unroll 4
    for (int kl = 0; kl < 64; kl += 2) {
        ulonglong2 nh0, nh1;
        float2 nA, nB;
        if (kl + 2 < 64) {
            nh0 = *(const ulonglong2*)(hr0 + 2 * (kbase + kl + 2));
            nh1 = *(const ulonglong2*)(hr1 + 2 * (kbase + kl + 2));
            nA = *(const float2*)(Wh + (size_t)(kl + 2) * Oo);
            nB = *(const float2*)(Wh + (size_t)(kl + 3) * Oo);
        }
        unsigned long long wA0, wA1, wB0, wB1;
        DUP2(wA0, wA.x); DUP2(wA1, wA.y);
        DUP2(wB0, wB.x); DUP2(wB1, wB.y);
        FMA2(acc2[0][0], h0.x, wA0); FMA2(acc2[0][1], h0.x, wA1);
        FMA2(acc2[1][0], h1.x, wA0); FMA2(acc2[1][1], h1.x, wA1);
        FMA2(acc2[0][0], h0.y, wB0); FMA2(acc2[0][1], h0.y, wB1);
        FMA2(acc2[1][0], h1.y, wB0); FMA2(acc2[1][1], h1.y, wB1);
        h0 = nh0; h1 = nh1; wA = nA; wB = nB;
    }
}

// ---------------- main fused MLP (R10 tiling + quarter-staged weights) --------
// SMEM = Wbuf 32KB (double-buffered 16KB quarters) + xp 16.6KB = 49.4KB
//   -> 3 CTAs/SM, 6 warps/SMSP, single balanced wave of 356 CTAs.
// Layer 1: warp = 8 pairs x 32 cols; lane = 2 pairs x 4 cols.
// Layer 2: warp = 8 pairs x 16 cols; lane = 2 pairs x 2 cols. h overwrites xp.
__global__ void __launch_bounds__(256, 3)
k_mlp(const float* __restrict__ x,
      const float* __restrict__ W1, const float* __restrict__ b1,
      const float* __restrict__ W2, const float* __restrict__ b2,
      float* __restrict__ out) {
    extern __shared__ float sm[];
    float* Wbuf = sm;                     // 8192 f : 2 x 16KB quarter buffers
    float* xp   = sm + 2 * 4096;          // 16*260 f : pair-major packed x / h

    int w = blockIdx.x;
    if (w >= g_numWork) return;
    int c     = g_workCat[w];
    int start = g_workStart[w];
    int cnt   = g_workCnt[w];
    int t = threadIdx.x;

    unsigned wba = (unsigned)__cvta_generic_to_shared(Wbuf);
    const float4* W1g = (const float4*)(W1 + (size_t)c * Dd * Hh);   // 4096 float4
    const float4* W2g = (const float4*)(W2 + (size_t)c * Hh * Oo);   // 2048 float4

    // issue W1 quarters 0,1 (one group each)
    #pragma unroll
    for (int i = t; i < QF; i += 256) CP_ASYNC16(wba + i * 16, W1g + i);
    CP_ASYNC_COMMIT();
    #pragma unroll
    for (int i = t; i < QF; i += 256) CP_ASYNC16(wba + 16384 + i * 16, W1g + QF + i);
    CP_ASYNC_COMMIT();

    // ---- stage x transposed+pair-packed: xp[p][d] = (x_{2p}[d], x_{2p+1}[d]) ----
    #pragma unroll
    for (int i = t; i < NPAIR * 32; i += 256) {
        int p = i >> 5, q = i & 31;
        int iA = 2 * p, iB = 2 * p + 1;
        int tA = (iA < cnt) ? g_perm[start + iA] : -1;
        int tB = (iB < cnt) ? g_perm[start + iB] : -1;
        float4 a = (tA >= 0) ? ((const float4*)(x + (size_t)tA * Dd))[q]
                             : make_float4(0.f, 0.f, 0.f, 0.f);
        float4 bb = (tB >= 0) ? ((const float4*)(x + (size_t)tB * Dd))[q]
                              : make_float4(0.f, 0.f, 0.f, 0.f);
        float* dst = xp + (size_t)p * XSTRIDE + 8 * q;
        ((float4*)dst)[0] = make_float4(a.x, bb.x, a.y, bb.y);
        ((float4*)dst)[1] = make_float4(a.z, bb.z, a.w, bb.w);
    }
    CP_ASYNC_WAIT1();      // quarter 0 landed
    __syncthreads();

    int warp = t >> 5, lane = t & 31;
    int pg = warp & 1;
    int cg = warp >> 1;
    int p0 = 8 * pg + 2 * (lane & 3);
    int cbase = 32 * cg + 4 * (lane >> 2);

    const float* xr0 = xp + (size_t)(p0 + 0) * XSTRIDE;
    const float* xr1 = xp + (size_t)(p0 + 1) * XSTRIDE;

    unsigned long long acc[2][4];
    #pragma unroll
    for (int pp = 0; pp < 2; pp++)
        #pragma unroll
        for (int jj = 0; jj < 4; jj++) acc[pp][jj] = 0ULL;

    // ---- layer 1: 4 quarters through double-buffered Wbuf ----
    // q0 (buf0)
    l1_quarter(acc, Wbuf + cbase, xr0, xr1, 0);
    __syncthreads();                                   // buf0 free
    #pragma unroll
    for (int i = t; i < QF; i += 256) CP_ASYNC16(wba + i * 16, W1g + 2 * QF + i);  // Q2 -> buf0
    CP_ASYNC_COMMIT();
    CP_ASYNC_WAIT1();                                  // Q1 landed
    __syncthreads();
    // q1 (buf1)
    l1_quarter(acc, Wbuf + 4096 + cbase, xr0, xr1, 32);
    __syncthreads();                                   // buf1 free
    #pragma unroll
    for (int i = t; i < QF; i += 256) CP_ASYNC16(wba + 16384 + i * 16, W1g + 3 * QF + i); // Q3 -> buf1
    CP_ASYNC_COMMIT();
    CP_ASYNC_WAIT1();                                  // Q2 landed
    __syncthreads();
    // q2 (buf0)
    l1_quarter(acc, Wbuf + cbase, xr0, xr1, 64);
    __syncthreads();                                   // buf0 free
    #pragma unroll
    for (int i = t; i < QF; i += 256) CP_ASYNC16(wba + i * 16, W2g + i);          // W2 half0 -> buf0
    CP_ASYNC_COMMIT();
    CP_ASYNC_WAIT1();                                  // Q3 landed
    __syncthreads();
    // q3 (buf1)
    l1_quarter(acc, Wbuf + 4096 + cbase, xr0, xr1, 96);
    __syncthreads();                                   // buf1 free; xp reads done
    #pragma unroll
    for (int i = t; i < QF; i += 256) CP_ASYNC16(wba + 16384 + i * 16, W2g + QF + i); // W2 half1 -> buf1
    CP_ASYNC_COMMIT();

    // epilogue 1: bias + relu, store pair-packed h in place over xp
    {
        float4 bv = *(const float4*)(b1 + (size_t)c * Hh + cbase);
        float bj[4] = {bv.x, bv.y, bv.z, bv.w};
        #pragma unroll
        for (int pp = 0; pp < 2; pp++) {
            ulonglong2 v;
            float l0, h0, l1, h1, l2, h2, l3, h3;
            UNPK2(l0, h0, acc[pp][0]);
            UNPK2(l1, h1, acc[pp][1]);
            UNPK2(l2, h2, acc[pp][2]);
            UNPK2(l3, h3, acc[pp][3]);
            l0 = fmaxf(l0 + bj[0], 0.f); h0 = fmaxf(h0 + bj[0], 0.f);
            l1 = fmaxf(l1 + bj[1], 0.f); h1 = fmaxf(h1 + bj[1], 0.f);
            PK2(v.x, l0, h0); PK2(v.y, l1, h1);
            *(ulonglong2*)(xp + (size_t)(p0 + pp) * XSTRIDE + 2 * cbase) = v;
            l2 = fmaxf(l2 + bj[2], 0.f); h2 = fmaxf(h2 + bj[2], 0.f);
            l3 = fmaxf(l3 + bj[3], 0.f); h3 = fmaxf(h3 + bj[3], 0.f);
            PK2(v.x, l2, h2); PK2(v.y, l3, h3);
            *(ulonglong2*)(xp + (size_t)(p0 + pp) * XSTRIDE + 2 * cbase + 4) = v;
        }
    }
    CP_ASYNC_WAIT0();      // both W2 halves landed
    __syncthreads();       // h visible to all warps

    // ---- layer 2: two halves from buf0 / buf1 ----
    int cb2 = 16 * cg + 2 * (lane >> 2);
    unsigned long long acc2[2][2];
    acc2[0][0] = acc2[0][1] = acc2[1][0] = acc2[1][1] = 0ULL;

    l2_half(acc2, Wbuf + cb2, xr0, xr1, 0);
    l2_half(acc2, Wbuf + 4096 + cb2, xr0, xr1, 64);

    // epilogue 2: bias + store (unpack token pairs)
    {
        float2 b2v = *(const float2*)(b2 + (size_t)c * Oo + cb2);
        #pragma unroll
        for (int pp = 0; pp < 2; pp++) {
            int iA = 2 * (p0 + pp), iB = iA + 1;
            int tA = (iA < cnt) ? g_perm[start + iA] : -1;
            int tB = (iB < cnt) ? g_perm[start + iB] : -1;
            float l0, h0, l1, h1;
            UNPK2(l0, h0, acc2[pp][0]);
            UNPK2(l1, h1, acc2[pp][1]);
            if (tA >= 0) {
                float2 o; o.x = l0 + b2v.x; o.y = l1 + b2v.y;
                *(float2*)(out + (size_t)tA * Oo + cb2) = o;
            }
            if (tB >= 0) {
                float2 o; o.x = h0 + b2v.x; o.y = h1 + b2v.y;
                *(float2*)(out + (size_t)tB * Oo + cb2) = o;
            }
        }
    }
}

extern "C" void kernel_launch(void* const* d_in, const int* in_sizes, int n_in,
                              void* d_out, int out_size) {
    const float* x   = (const float*)d_in[0];
    const int*   cat = (const int*)  d_in[1];
    const float* W1  = (const float*)d_in[2];
    const float* b1  = (const float*)d_in[3];
    const float* W2  = (const float*)d_in[4];
    const float* b2  = (const float*)d_in[5];
    float* out = (float*)d_out;

    size_t smem = (size_t)(2 * 4096 + NPAIR * XSTRIDE) * sizeof(float); // 49408 B
    static bool attr_set = false;
    if (!attr_set) {
        cudaFuncSetAttribute(k_mlp, cudaFuncAttributeMaxDynamicSharedMemorySize, (int)smem);
        attr_set = true;
    }

    k_sort<<<NB, BT>>>(cat);
    k_mlp<<<MAXW, 256, smem>>>(x, W1, b1, W2, b2, out);
}

// round 13
// speedup vs baseline: 1.0874x; 1.0077x over previous
#include <cuda_runtime.h>

#define Nn 8192
#define Cc 100
#define Dd 128
#define Hh 128
#define Oo 64
#define TPC 48                 // tokens per CTA chunk -> ~205 chunks < 296 slots: 1 wave
#define NPAIR (TPC / 2)        // 24 token pairs
#define XSTRIDE 260            // words per pair-row (1040 B: 16B-aligned, bank-spread)
#define MAXW 272               // worst-case Sum ceil(n_c/48) <= 270
#define NB 16
#define BT 512

// ---------------- packed f32x2 helpers ----------------
#define FMA2(d, a, b) asm("fma.rn.f32x2 %0, %1, %2, %0;" : "+l"(d) : "l"(a), "l"(b))
#define DUP2(d, s)    asm("mov.b64 %0, {%1, %1};" : "=l"(d) : "f"(s))
#define PK2(d, lo, hi) asm("mov.b64 %0, {%1, %2};" : "=l"(d) : "f"(lo), "f"(hi))
#define UNPK2(lo, hi, s) asm("mov.b64 {%0, %1}, %2;" : "=f"(lo), "=f"(hi) : "l"(s))
#define CP_ASYNC16(smem_u32, gptr) \
    asm volatile("cp.async.cg.shared.global [%0], [%1], 16;" :: "r"(smem_u32), "l"(gptr))
#define CP_ASYNC_COMMIT() asm volatile("cp.async.commit_group;")
#define CP_ASYNC_WAIT0()  asm volatile("cp.async.wait_group 0;")

// ---------------- scratch (no allocations allowed) ----------------
__device__ int g_perm[Nn];
__device__ int g_workCat[MAXW];
__device__ int g_workStart[MAXW];
__device__ int g_workCnt[MAXW];
__device__ int g_numWork;

// ---------------- single-launch counting sort ----------------
__global__ void __launch_bounds__(BT) k_sort(const int* __restrict__ cat) {
    __shared__ int h_tot[128];
    __shared__ int h_pre[128];
    __shared__ int s_scan[128];
    int t = threadIdx.x, b = blockIdx.x;
    if (t < 128) { h_tot[t] = 0; h_pre[t] = 0; }
    __syncthreads();

    int myseg = b * BT;
    #pragma unroll 4
    for (int i = t; i < Nn; i += BT) {
        int c = cat[i];
        atomicAdd(&h_tot[c], 1);
        if (i < myseg) atomicAdd(&h_pre[c], 1);
    }
    __syncthreads();

    int p_mine = 0;
    if (t < 128) {
        int tot = (t < Cc) ? h_tot[t] : 0;
        p_mine = tot | (((tot + TPC - 1) / TPC) << 16);
        s_scan[t] = p_mine;
    }
    __syncthreads();
    #pragma unroll
    for (int d = 1; d < 128; d <<= 1) {
        int v = 0;
        if (t < 128 && t >= d) v = s_scan[t - d];
        __syncthreads();
        if (t < 128) s_scan[t] += v;
        __syncthreads();
    }

    if (t < Cc) {
        int excl = s_scan[t] - p_mine;
        int offEx = excl & 0xFFFF;
        h_pre[t] += offEx;
        if (b == 0) {
            int coffEx = excl >> 16;
            int tot = p_mine & 0xFFFF;
            int nch = p_mine >> 16;
            for (int j = 0; j < nch; j++) {
                g_workCat[coffEx + j]   = t;
                g_workStart[coffEx + j] = offEx + j * TPC;
                int rem = tot - j * TPC;
                g_workCnt[coffEx + j]   = rem < TPC ? rem : TPC;
            }
        }
    }
    if (b == 0 && t == 127) g_numWork = s_scan[127] >> 16;
    __syncthreads();

    int id = myseg + t;
    int pos = atomicAdd(&h_pre[cat[id]], 1);
    g_perm[pos] = id;
}

// ---------------- main fused MLP (TPC=48, W2 reuses W1 buffer) ----------------
// SMEM = Wbuf 64KB (W1 phase 1, W2 phase 2) + xp 24.4KB = 90.5KB -> 2 CTAs/SM.
// ~205 chunks <= 296 slots -> SINGLE WAVE (the R10 tail is gone).
// Layer 1: warp = 12 pairs x 32 cols; lane = 3 pairs x 4 cols (4.8 FMA2/wf).
// Layer 2: warp = 12 pairs x 16 cols; lane = 3 pairs x 2 cols. h overwrites xp.
__global__ void __launch_bounds__(256, 2)
k_mlp(const float* __restrict__ x,
      const float* __restrict__ W1, const float* __restrict__ b1,
      const float* __restrict__ W2, const float* __restrict__ b2,
      float* __restrict__ out) {
    extern __shared__ float sm[];
    float* Wbuf = sm;                     // 16384 f (64KB): W1 [d][h], then W2 [k][o]
    float* xp   = sm + Dd * Hh;           // 24*260 f : pair-major packed x / h

    int w = blockIdx.x;
    if (w >= g_numWork) return;
    int c     = g_workCat[w];
    int start = g_workStart[w];
    int cnt   = g_workCnt[w];
    int t = threadIdx.x;

    unsigned wba = (unsigned)__cvta_generic_to_shared(Wbuf);
    const float4* W1g = (const float4*)(W1 + (size_t)c * Dd * Hh);   // 4096 float4
    const float4* W2g = (const float4*)(W2 + (size_t)c * Hh * Oo);   // 2048 float4

    // ---- stage W1 via cp.async (overlaps x gather) ----
    #pragma unroll
    for (int i = t; i < Dd * Hh / 4; i += 256) CP_ASYNC16(wba + i * 16, W1g + i);
    CP_ASYNC_COMMIT();

    // ---- stage x transposed+pair-packed: xp[p][d] = (x_{2p}[d], x_{2p+1}[d]) ----
    #pragma unroll
    for (int i = t; i < NPAIR * 32; i += 256) {
        int p = i >> 5, q = i & 31;            // q indexes d-quads
        int iA = 2 * p, iB = 2 * p + 1;
        int tA = (iA < cnt) ? g_perm[start + iA] : -1;
        int tB = (iB < cnt) ? g_perm[start + iB] : -1;
        float4 a = (tA >= 0) ? ((const float4*)(x + (size_t)tA * Dd))[q]
                             : make_float4(0.f, 0.f, 0.f, 0.f);
        float4 bb = (tB >= 0) ? ((const float4*)(x + (size_t)tB * Dd))[q]
                              : make_float4(0.f, 0.f, 0.f, 0.f);
        float* dst = xp + (size_t)p * XSTRIDE + 8 * q;
        ((float4*)dst)[0] = make_float4(a.x, bb.x, a.y, bb.y);
        ((float4*)dst)[1] = make_float4(a.z, bb.z, a.w, bb.w);
    }
    CP_ASYNC_WAIT0();
    __syncthreads();

    int warp = t >> 5, lane = t & 31;
    int pg = warp & 1;                     // pair half (12 pairs)
    int cg = warp >> 1;                    // col group (32 cols)
    int p0 = 12 * pg + 3 * (lane & 3);     // lane's 3 pairs (bank phases 0/48/96/16)
    int cbase = 32 * cg + 4 * (lane >> 2); // lane's 4 H-cols
    bool act = (24 * pg < cnt);            // pair half has at least one real token

    // ---- layer 1: software-pipelined; acc[pair][col] = 12 packed accumulators ----
    unsigned long long acc[3][4];
    #pragma unroll
    for (int pp = 0; pp < 3; pp++)
        #pragma unroll
        for (int jj = 0; jj < 4; jj++) acc[pp][jj] = 0ULL;

    const float* xr0 = xp + (size_t)(p0 + 0) * XSTRIDE;
    const float* xr1 = xp + (size_t)(p0 + 1) * XSTRIDE;
    const float* xr2 = xp + (size_t)(p0 + 2) * XSTRIDE;

    if (act) {
        const float* Wr = Wbuf + cbase;
        ulonglong2 xv0 = *(const ulonglong2*)(xr0);
        ulonglong2 xv1 = *(const ulonglong2*)(xr1);
        ulonglong2 xv2 = *(const ulonglong2*)(xr2);
        float4 wa = *(const float4*)(Wr);
        float4 wb = *(const float4*)(Wr + Hh);
        #pragma unroll 4
        for (int d = 0; d < Dd; d += 2) {
            ulonglong2 nx0, nx1, nx2;
            float4 nwa, nwb;
            if (d + 2 < Dd) {
                nx0 = *(const ulonglong2*)(xr0 + 2 * (d + 2));
                nx1 = *(const ulonglong2*)(xr1 + 2 * (d + 2));
                nx2 = *(const ulonglong2*)(xr2 + 2 * (d + 2));
                nwa = *(const float4*)(Wr + (size_t)(d + 2) * Hh);
                nwb = *(const float4*)(Wr + (size_t)(d + 3) * Hh);
            }
            unsigned long long a0, a1, a2w, a3, b0, b1, b2w, b3;
            DUP2(a0, wa.x); DUP2(a1, wa.y); DUP2(a2w, wa.z); DUP2(a3, wa.w);
            DUP2(b0, wb.x); DUP2(b1, wb.y); DUP2(b2w, wb.z); DUP2(b3, wb.w);
            FMA2(acc[0][0], xv0.x, a0); FMA2(acc[0][1], xv0.x, a1);
            FMA2(acc[0][2], xv0.x, a2w); FMA2(acc[0][3], xv0.x, a3);
            FMA2(acc[1][0], xv1.x, a0); FMA2(acc[1][1], xv1.x, a1);
            FMA2(acc[1][2], xv1.x, a2w); FMA2(acc[1][3], xv1.x, a3);
            FMA2(acc[2][0], xv2.x, a0); FMA2(acc[2][1], xv2.x, a1);
            FMA2(acc[2][2], xv2.x, a2w); FMA2(acc[2][3], xv2.x, a3);
            FMA2(acc[0][0], xv0.y, b0); FMA2(acc[0][1], xv0.y, b1);
            FMA2(acc[0][2], xv0.y, b2w); FMA2(acc[0][3], xv0.y, b3);
            FMA2(acc[1][0], xv1.y, b0); FMA2(acc[1][1], xv1.y, b1);
            FMA2(acc[1][2], xv1.y, b2w); FMA2(acc[1][3], xv1.y, b3);
            FMA2(acc[2][0], xv2.y, b0); FMA2(acc[2][1], xv2.y, b1);
            FMA2(acc[2][2], xv2.y, b2w); FMA2(acc[2][3], xv2.y, b3);
            xv0 = nx0; xv1 = nx1; xv2 = nx2; wa = nwa; wb = nwb;
        }
    }

    __syncthreads();   // all reads of W1 and xp complete

    // ---- stage W2 into Wbuf (reuse) — overlaps epilogue 1 ----
    #pragma unroll
    for (int i = t; i < Hh * Oo / 4; i += 256) CP_ASYNC16(wba + i * 16, W2g + i);
    CP_ASYNC_COMMIT();

    // epilogue 1: bias + relu, store pair-packed h in place over xp
    if (act) {
        float4 bv = *(const float4*)(b1 + (size_t)c * Hh + cbase);
        float bj[4] = {bv.x, bv.y, bv.z, bv.w};
        #pragma unroll
        for (int pp = 0; pp < 3; pp++) {
            ulonglong2 v;
            float l0, h0, l1, h1, l2, h2, l3, h3;
            UNPK2(l0, h0, acc[pp][0]);
            UNPK2(l1, h1, acc[pp][1]);
            UNPK2(l2, h2, acc[pp][2]);
            UNPK2(l3, h3, acc[pp][3]);
            l0 = fmaxf(l0 + bj[0], 0.f); h0 = fmaxf(h0 + bj[0], 0.f);
            l1 = fmaxf(l1 + bj[1], 0.f); h1 = fmaxf(h1 + bj[1], 0.f);
            PK2(v.x, l0, h0); PK2(v.y, l1, h1);
            *(ulonglong2*)(xp + (size_t)(p0 + pp) * XSTRIDE + 2 * cbase) = v;
            l2 = fmaxf(l2 + bj[2], 0.f); h2 = fmaxf(h2 + bj[2], 0.f);
            l3 = fmaxf(l3 + bj[3], 0.f); h3 = fmaxf(h3 + bj[3], 0.f);
            PK2(v.x, l2, h2); PK2(v.y, l3, h3);
            *(ulonglong2*)(xp + (size_t)(p0 + pp) * XSTRIDE + 2 * cbase + 4) = v;
        }
    }
    CP_ASYNC_WAIT0();
    __syncthreads();   // h visible + W2 staged

    // ---- layer 2: software-pipelined; acc2[pair][col] = 6 packed accumulators ----
    int cb2 = 16 * cg + 2 * (lane >> 2);   // lane's 2 O-cols
    unsigned long long acc2[3][2];
    #pragma unroll
    for (int pp = 0; pp < 3; pp++) { acc2[pp][0] = 0ULL; acc2[pp][1] = 0ULL; }

    if (act) {
        const float* Wr2 = Wbuf + cb2;
        ulonglong2 h0 = *(const ulonglong2*)(xr0);
        ulonglong2 h1 = *(const ulonglong2*)(xr1);
        ulonglong2 h2 = *(const ulonglong2*)(xr2);
        float2 wA = *(const float2*)(Wr2);
        float2 wB = *(const float2*)(Wr2 + Oo);
        #pragma unroll 4
        for (int k = 0; k < Hh; k += 2) {
            ulonglong2 nh0, nh1, nh2;
            float2 nA, nB;
            if (k + 2 < Hh) {
                nh0 = *(const ulonglong2*)(xr0 + 2 * (k + 2));
                nh1 = *(const ulonglong2*)(xr1 + 2 * (k + 2));
                nh2 = *(const ulonglong2*)(xr2 + 2 * (k + 2));
                nA = *(const float2*)(Wr2 + (size_t)(k + 2) * Oo);
                nB = *(const float2*)(Wr2 + (size_t)(k + 3) * Oo);
            }
            unsigned long long wA0, wA1, wB0, wB1;
            DUP2(wA0, wA.x); DUP2(wA1, wA.y);
            DUP2(wB0, wB.x); DUP2(wB1, wB.y);
            FMA2(acc2[0][0], h0.x, wA0); FMA2(acc2[0][1], h0.x, wA1);
            FMA2(acc2[1][0], h1.x, wA0); FMA2(acc2[1][1], h1.x, wA1);
            FMA2(acc2[2][0], h2.x, wA0); FMA2(acc2[2][1], h2.x, wA1);
            FMA2(acc2[0][0], h0.y, wB0); FMA2(acc2[0][1], h0.y, wB1);
            FMA2(acc2[1][0], h1.y, wB0); FMA2(acc2[1][1], h1.y, wB1);
            FMA2(acc2[2][0], h2.y, wB0); FMA2(acc2[2][1], h2.y, wB1);
            h0 = nh0; h1 = nh1; h2 = nh2; wA = nA; wB = nB;
        }

        // epilogue 2: bias + store (unpack token pairs)
        float2 b2v = *(const float2*)(b2 + (size_t)c * Oo + cb2);
        #pragma unroll
        for (int pp = 0; pp < 3; pp++) {
            int iA = 2 * (p0 + pp), iB = iA + 1;
            int tA = (iA < cnt) ? g_perm[start + iA] : -1;
            int tB = (iB < cnt) ? g_perm[start + iB] : -1;
            float l0, h0f, l1, h1f;
            UNPK2(l0, h0f, acc2[pp][0]);
            UNPK2(l1, h1f, acc2[pp][1]);
            if (tA >= 0) {
                float2 o; o.x = l0 + b2v.x; o.y = l1 + b2v.y;
                *(float2*)(out + (size_t)tA * Oo + cb2) = o;
            }
            if (tB >= 0) {
                float2 o; o.x = h0f + b2v.x; o.y = h1f + b2v.y;
                *(float2*)(out + (size_t)tB * Oo + cb2) = o;
            }
        }
    }
}

extern "C" void kernel_launch(void* const* d_in, const int* in_sizes, int n_in,
                              void* d_out, int out_size) {
    const float* x   = (const float*)d_in[0];
    const int*   cat = (const int*)  d_in[1];
    const float* W1  = (const float*)d_in[2];
    const float* b1  = (const float*)d_in[3];
    const float* W2  = (const float*)d_in[4];
    const float* b2  = (const float*)d_in[5];
    float* out = (float*)d_out;

    size_t smem = (size_t)(Dd * Hh + NPAIR * XSTRIDE) * sizeof(float); // 90496 B
    static bool attr_set = false;
    if (!attr_set) {
        cudaFuncSetAttribute(k_mlp, cudaFuncAttributeMaxDynamicSharedMemorySize, (int)smem);
        attr_set = true;
    }

    k_sort<<<NB, BT>>>(cat);
    k_mlp<<<MAXW, 256, smem>>>(x, W1, b1, W2, b2, out);
}

// round 15
// speedup vs baseline: 1.2538x; 1.1531x over previous
#include <cuda_runtime.h>
#include <cuda_bf16.h>
#include <cstdint>

#define Nn 8192
#define Cc 100
#define Dd 128
#define Hh 128
#define Oo 64
#define TPC 128
#define MAXW 168
#define NB 16
#define BT 512

#define KSB 272                      // smem row stride in bytes (136 bf16): conflict-free
#define SM_A_HI 0
#define SM_A_LO 34816
#define SM_B_HI 69632
#define SM_B_LO 104448
#define SMEM_TOTAL 139264

// d += a * b  (m16n8k16 row.col bf16 -> f32)
#define MMA16816(d, a, b) \
    asm volatile("mma.sync.aligned.m16n8k16.row.col.f32.bf16.bf16.f32 " \
        "{%0,%1,%2,%3}, {%4,%5,%6,%7}, {%8,%9}, {%0,%1,%2,%3};" \
        : "+f"((d)[0]), "+f"((d)[1]), "+f"((d)[2]), "+f"((d)[3]) \
        : "r"((a)[0]), "r"((a)[1]), "r"((a)[2]), "r"((a)[3]), "r"((b)[0]), "r"((b)[1]))

// bf16 hi/lo split of two floats; low-order element in low 16 bits
__device__ __forceinline__ void split2(float a, float b, uint32_t& hi, uint32_t& lo) {
    __nv_bfloat16 ah = __float2bfloat16(a), bh = __float2bfloat16(b);
    float ar = a - __bfloat162float(ah), br = b - __bfloat162float(bh);
    __nv_bfloat162 hp, lp;
    hp.x = ah; hp.y = bh;
    lp.x = __float2bfloat16(ar); lp.y = __float2bfloat16(br);
    hi = *(uint32_t*)&hp; lo = *(uint32_t*)&lp;
}

// ---------------- scratch ----------------
__device__ int g_perm[Nn];
__device__ int g_workCat[MAXW];
__device__ int g_workStart[MAXW];
__device__ int g_workCnt[MAXW];
__device__ int g_numWork;

// ---------------- single-launch counting sort (TPC=128 chunks) ----------------
__global__ void __launch_bounds__(BT) k_sort(const int* __restrict__ cat) {
    __shared__ int h_tot[128];
    __shared__ int h_pre[128];
    __shared__ int s_scan[128];
    int t = threadIdx.x, b = blockIdx.x;
    if (t < 128) { h_tot[t] = 0; h_pre[t] = 0; }
    __syncthreads();
    int myseg = b * BT;
    #pragma unroll 4
    for (int i = t; i < Nn; i += BT) {
        int c = cat[i];
        atomicAdd(&h_tot[c], 1);
        if (i < myseg) atomicAdd(&h_pre[c], 1);
    }
    __syncthreads();
    int p_mine = 0;
    if (t < 128) {
        int tot = (t < Cc) ? h_tot[t] : 0;
        p_mine = tot | (((tot + TPC - 1) / TPC) << 16);
        s_scan[t] = p_mine;
    }
    __syncthreads();
    #pragma unroll
    for (int d = 1; d < 128; d <<= 1) {
        int v = 0;
        if (t < 128 && t >= d) v = s_scan[t - d];
        __syncthreads();
        if (t < 128) s_scan[t] += v;
        __syncthreads();
    }
    if (t < Cc) {
        int excl = s_scan[t] - p_mine;
        int offEx = excl & 0xFFFF;
        h_pre[t] += offEx;
        if (b == 0) {
            int coffEx = excl >> 16;
            int tot = p_mine & 0xFFFF;
            int nch = p_mine >> 16;
            for (int j = 0; j < nch; j++) {
                g_workCat[coffEx + j]   = t;
                g_workStart[coffEx + j] = offEx + j * TPC;
                int rem = tot - j * TPC;
                g_workCnt[coffEx + j]   = rem < TPC ? rem : TPC;
            }
        }
    }
    if (b == 0 && t == 127) g_numWork = s_scan[127] >> 16;
    __syncthreads();
    int id = myseg + t;
    int pos = atomicAdd(&h_pre[cat[id]], 1);
    g_perm[pos] = id;
}

// ---------------- tensor-core MLP via mma.sync (HMMA) ----------------
// One CTA = (category, 128-token tile). bf16 hi/lo 3-term MMAs, fp32 accum.
// Warp (wm = warp>>1, wn = warp&1): layer1 = 2 m-tiles x 8 n-tiles,
// layer2 = 2 m-tiles x 4 n-tiles. A rows are warp-private; h overwrites A.
__global__ void __launch_bounds__(256, 1)
k_mlp(const float* __restrict__ x,
      const float* __restrict__ W1, const float* __restrict__ b1,
      const float* __restrict__ W2, const float* __restrict__ b2,
      float* __restrict__ out) {
    extern __shared__ char smem[];
    char* smA_hi = smem + SM_A_HI;
    char* smA_lo = smem + SM_A_LO;
    char* smB_hi = smem + SM_B_HI;
    char* smB_lo = smem + SM_B_LO;

    int w = blockIdx.x;
    if (w >= g_numWork) return;
    int c = g_workCat[w], start = g_workStart[w], cnt = g_workCnt[w];
    int tid = threadIdx.x, warp = tid >> 5, lane = tid & 31;

    // ---- stage A = x rows (bf16 hi/lo), rows m = token index in chunk ----
    #pragma unroll 4
    for (int i = tid; i < TPC * 32; i += 256) {
        int m = i >> 5, q = i & 31;       // q = float4 index (k = 4q)
        int tk = (m < cnt) ? g_perm[start + m] : -1;
        float4 v = (tk >= 0) ? __ldg((const float4*)(x + (size_t)tk * Dd) + q)
                             : make_float4(0.f, 0.f, 0.f, 0.f);
        uint32_t h0, l0, h1, l1;
        split2(v.x, v.y, h0, l0);
        split2(v.z, v.w, h1, l1);
        uint32_t off = (uint32_t)m * KSB + (uint32_t)q * 8;
        *(uint2*)(smA_hi + off) = make_uint2(h0, h1);
        *(uint2*)(smA_lo + off) = make_uint2(l0, l1);
    }

    // ---- stage B1 = W1^T: rows n = H col, k = D (d-pairs packed) ----
    {
        const float* W1c = W1 + (size_t)c * Dd * Hh;
        #pragma unroll 4
        for (int i = tid; i < (Dd / 2) * Hh; i += 256) {
            int d2 = i >> 7, h = i & 127;
            const float* p = W1c + (size_t)(2 * d2) * Hh + h;
            float v0 = __ldg(p), v1 = __ldg(p + Hh);
            uint32_t hp, lp;
            split2(v0, v1, hp, lp);
            uint32_t off = (uint32_t)h * KSB + (uint32_t)d2 * 4;
            *(uint32_t*)(smB_hi + off) = hp;
            *(uint32_t*)(smB_lo + off) = lp;
        }
    }
    __syncthreads();

    int wm = warp >> 1, wn = warp & 1;
    int g = lane >> 2, tg = lane & 3;
    int mb = wm * 32;

    // ================= layer 1: M128 x N128 x K128 =================
    float acc[2][8][4];
    #pragma unroll
    for (int mt = 0; mt < 2; mt++)
        #pragma unroll
        for (int nt = 0; nt < 8; nt++)
            #pragma unroll
            for (int j = 0; j < 4; j++) acc[mt][nt][j] = 0.f;

    {
        int nb = wn * 64;
        #pragma unroll 1
        for (int kt = 0; kt < 8; kt++) {
            uint32_t kb = (uint32_t)kt * 32 + (uint32_t)tg * 4;
            uint32_t aHi[2][4], aLo[2][4];
            #pragma unroll
            for (int mt = 0; mt < 2; mt++) {
                uint32_t base = (uint32_t)(mb + mt * 16 + g) * KSB + kb;
                aHi[mt][0] = *(uint32_t*)(smA_hi + base);
                aHi[mt][1] = *(uint32_t*)(smA_hi + base + 8 * KSB);
                aHi[mt][2] = *(uint32_t*)(smA_hi + base + 16);
                aHi[mt][3] = *(uint32_t*)(smA_hi + base + 8 * KSB + 16);
                aLo[mt][0] = *(uint32_t*)(smA_lo + base);
                aLo[mt][1] = *(uint32_t*)(smA_lo + base + 8 * KSB);
                aLo[mt][2] = *(uint32_t*)(smA_lo + base + 16);
                aLo[mt][3] = *(uint32_t*)(smA_lo + base + 8 * KSB + 16);
            }
            #pragma unroll
            for (int nt = 0; nt < 8; nt++) {
                uint32_t bbase = (uint32_t)(nb + nt * 8 + g) * KSB + kb;
                uint32_t bHi[2], bLo[2];
                bHi[0] = *(uint32_t*)(smB_hi + bbase);
                bHi[1] = *(uint32_t*)(smB_hi + bbase + 16);
                bLo[0] = *(uint32_t*)(smB_lo + bbase);
                bLo[1] = *(uint32_t*)(smB_lo + bbase + 16);
                #pragma unroll
                for (int mt = 0; mt < 2; mt++) {
                    MMA16816(acc[mt][nt], aHi[mt], bHi);
                    MMA16816(acc[mt][nt], aLo[mt], bHi);
                    MMA16816(acc[mt][nt], aHi[mt], bLo);
                }
            }
        }

        // ---- h = relu(D1 + b1) -> bf16 hi/lo back into A (own rows/cols only) ----
        const float* b1c = b1 + (size_t)c * Hh;
        #pragma unroll
        for (int nt = 0; nt < 8; nt++) {
            int col = nb + nt * 8 + tg * 2;
            float bc0 = __ldg(b1c + col), bc1 = __ldg(b1c + col + 1);
            #pragma unroll
            for (int mt = 0; mt < 2; mt++) {
                int r0 = mb + mt * 16 + g;
                float v00 = fmaxf(acc[mt][nt][0] + bc0, 0.f);
                float v01 = fmaxf(acc[mt][nt][1] + bc1, 0.f);
                float v10 = fmaxf(acc[mt][nt][2] + bc0, 0.f);
                float v11 = fmaxf(acc[mt][nt][3] + bc1, 0.f);
                uint32_t hp0, lp0, hp1, lp1;
                split2(v00, v01, hp0, lp0);
                split2(v10, v11, hp1, lp1);
                uint32_t o0 = (uint32_t)r0 * KSB + (uint32_t)col * 2;
                uint32_t o1 = (uint32_t)(r0 + 8) * KSB + (uint32_t)col * 2;
                *(uint32_t*)(smA_hi + o0) = hp0;
                *(uint32_t*)(smA_lo + o0) = lp0;
                *(uint32_t*)(smA_hi + o1) = hp1;
                *(uint32_t*)(smA_lo + o1) = lp1;
            }
        }
    }
    __syncthreads();   // all B1 reads + h writes done

    // ---- stage B2 = W2^T: rows n = O col, k = H (h-pairs packed) ----
    {
        const float* W2c = W2 + (size_t)c * Hh * Oo;
        #pragma unroll 4
        for (int i = tid; i < (Hh / 2) * Oo; i += 256) {
            int k2 = i >> 6, o = i & 63;
            const float* p = W2c + (size_t)(2 * k2) * Oo + o;
            float v0 = __ldg(p), v1 = __ldg(p + Oo);
            uint32_t hp, lp;
            split2(v0, v1, hp, lp);
            uint32_t off = (uint32_t)o * KSB + (uint32_t)k2 * 4;
            *(uint32_t*)(smB_hi + off) = hp;
            *(uint32_t*)(smB_lo + off) = lp;
        }
    }
    __syncthreads();   // h visible to sibling warps + B2 staged

    // ================= layer 2: M128 x N64 x K128 =================
    float acc2[2][4][4];
    #pragma unroll
    for (int mt = 0; mt < 2; mt++)
        #pragma unroll
        for (int nt = 0; nt < 4; nt++)
            #pragma unroll
            for (int j = 0; j < 4; j++) acc2[mt][nt][j] = 0.f;

    {
        int nb2 = wn * 32;
        #pragma unroll 1
        for (int kt = 0; kt < 8; kt++) {
            uint32_t kb = (uint32_t)kt * 32 + (uint32_t)tg * 4;
            uint32_t aHi[2][4], aLo[2][4];
            #pragma unroll
            for (int mt = 0; mt < 2; mt++) {
                uint32_t base = (uint32_t)(mb + mt * 16 + g) * KSB + kb;
                aHi[mt][0] = *(uint32_t*)(smA_hi + base);
                aHi[mt][1] = *(uint32_t*)(smA_hi + base + 8 * KSB);
                aHi[mt][2] = *(uint32_t*)(smA_hi + base + 16);
                aHi[mt][3] = *(uint32_t*)(smA_hi + base + 8 * KSB + 16);
                aLo[mt][0] = *(uint32_t*)(smA_lo + base);
                aLo[mt][1] = *(uint32_t*)(smA_lo + base + 8 * KSB);
                aLo[mt][2] = *(uint32_t*)(smA_lo + base + 16);
                aLo[mt][3] = *(uint32_t*)(smA_lo + base + 8 * KSB + 16);
            }
            #pragma unroll
            for (int nt = 0; nt < 4; nt++) {
                uint32_t bbase = (uint32_t)(nb2 + nt * 8 + g) * KSB + kb;
                uint32_t bHi[2], bLo[2];
                bHi[0] = *(uint32_t*)(smB_hi + bbase);
                bHi[1] = *(uint32_t*)(smB_hi + bbase + 16);
                bLo[0] = *(uint32_t*)(smB_lo + bbase);
                bLo[1] = *(uint32_t*)(smB_lo + bbase + 16);
                #pragma unroll
                for (int mt = 0; mt < 2; mt++) {
                    MMA16816(acc2[mt][nt], aHi[mt], bHi);
                    MMA16816(acc2[mt][nt], aLo[mt], bHi);
                    MMA16816(acc2[mt][nt], aHi[mt], bLo);
                }
            }
        }

        // ---- out = D2 + b2 ----
        const float* b2c = b2 + (size_t)c * Oo;
        #pragma unroll
        for (int nt = 0; nt < 4; nt++) {
            int col = nb2 + nt * 8 + tg * 2;
            float bc0 = __ldg(b2c + col), bc1 = __ldg(b2c + col + 1);
            #pragma unroll
            for (int mt = 0; mt < 2; mt++) {
                int r0 = mb + mt * 16 + g;
                if (r0 < cnt) {
                    int tk = g_perm[start + r0];
                    float2 o;
                    o.x = acc2[mt][nt][0] + bc0;
                    o.y = acc2[mt][nt][1] + bc1;
                    *(float2*)(out + (size_t)tk * Oo + col) = o;
                }
                int r1 = r0 + 8;
                if (r1 < cnt) {
                    int tk = g_perm[start + r1];
                    float2 o;
                    o.x = acc2[mt][nt][2] + bc0;
                    o.y = acc2[mt][nt][3] + bc1;
                    *(float2*)(out + (size_t)tk * Oo + col) = o;
                }
            }
        }
    }
}

extern "C" void kernel_launch(void* const* d_in, const int* in_sizes, int n_in,
                              void* d_out, int out_size) {
    const float* x   = (const float*)d_in[0];
    const int*   cat = (const int*)  d_in[1];
    const float* W1  = (const float*)d_in[2];
    const float* b1  = (const float*)d_in[3];
    const float* W2  = (const float*)d_in[4];
    const float* b2  = (const float*)d_in[5];
    float* out = (float*)d_out;

    static bool attr_set = false;
    if (!attr_set) {
        cudaFuncSetAttribute(k_mlp, cudaFuncAttributeMaxDynamicSharedMemorySize, SMEM_TOTAL);
        attr_set = true;
    }

    k_sort<<<NB, BT>>>(cat);
    k_mlp<<<MAXW, 256, SMEM_TOTAL>>>(x, W1, b1, W2, b2, out);
}

// round 17
// speedup vs baseline: 1.3963x; 1.1136x over previous
#include <cuda_runtime.h>
#include <cuda_bf16.h>
#include <cstdint>

#define Nn 8192
#define Cc 100
#define Dd 128
#define Hh 128
#define Oo 64
#define TPC 128
#define MAXW 168
#define NB 16
#define BT 512

#define KSB 272                      // smem row stride in bytes (136 bf16): conflict-free
#define SM_A_HI  0
#define SM_A_LO  34816
#define SM_H_HI  69632               // B1 during layer 1, h during layer 2
#define SM_H_LO  104448
#define SM_B2_HI 139264
#define SM_B2_LO 156672
#define SMEM_TOTAL 174080

// d += a * b  (m16n8k16 row.col bf16 -> f32)
#define MMA16816(d, a, b) \
    asm volatile("mma.sync.aligned.m16n8k16.row.col.f32.bf16.bf16.f32 " \
        "{%0,%1,%2,%3}, {%4,%5,%6,%7}, {%8,%9}, {%0,%1,%2,%3};" \
        : "+f"((d)[0]), "+f"((d)[1]), "+f"((d)[2]), "+f"((d)[3]) \
        : "r"((a)[0]), "r"((a)[1]), "r"((a)[2]), "r"((a)[3]), "r"((b)[0]), "r"((b)[1]))

// bf16 hi/lo split of two floats; low-order element in low 16 bits
__device__ __forceinline__ void split2(float a, float b, uint32_t& hi, uint32_t& lo) {
    __nv_bfloat16 ah = __float2bfloat16(a), bh = __float2bfloat16(b);
    float ar = a - __bfloat162float(ah), br = b - __bfloat162float(bh);
    __nv_bfloat162 hp, lp;
    hp.x = ah; hp.y = bh;
    lp.x = __float2bfloat16(ar); lp.y = __float2bfloat16(br);
    hi = *(uint32_t*)&hp; lo = *(uint32_t*)&lp;
}

// ---------------- scratch ----------------
__device__ int g_perm[Nn];
__device__ int g_workCat[MAXW];
__device__ int g_workStart[MAXW];
__device__ int g_workCnt[MAXW];
__device__ int g_numWork;

// ---------------- single-launch counting sort (TPC=128 chunks) ----------------
__global__ void __launch_bounds__(BT) k_sort(const int* __restrict__ cat) {
    __shared__ int h_tot[128];
    __shared__ int h_pre[128];
    __shared__ int s_scan[128];
    int t = threadIdx.x, b = blockIdx.x;
    if (t < 128) { h_tot[t] = 0; h_pre[t] = 0; }
    __syncthreads();
    int myseg = b * BT;
    #pragma unroll 4
    for (int i = t; i < Nn; i += BT) {
        int c = cat[i];
        atomicAdd(&h_tot[c], 1);
        if (i < myseg) atomicAdd(&h_pre[c], 1);
    }
    __syncthreads();
    int p_mine = 0;
    if (t < 128) {
        int tot = (t < Cc) ? h_tot[t] : 0;
        p_mine = tot | (((tot + TPC - 1) / TPC) << 16);
        s_scan[t] = p_mine;
    }
    __syncthreads();
    #pragma unroll
    for (int d = 1; d < 128; d <<= 1) {
        int v = 0;
        if (t < 128 && t >= d) v = s_scan[t - d];
        __syncthreads();
        if (t < 128) s_scan[t] += v;
        __syncthreads();
    }
    if (t < Cc) {
        int excl = s_scan[t] - p_mine;
        int offEx = excl & 0xFFFF;
        h_pre[t] += offEx;
        if (b == 0) {
            int coffEx = excl >> 16;
            int tot = p_mine & 0xFFFF;
            int nch = p_mine >> 16;
            for (int j = 0; j < nch; j++) {
                g_workCat[coffEx + j]   = t;
                g_workStart[coffEx + j] = offEx + j * TPC;
                int rem = tot - j * TPC;
                g_workCnt[coffEx + j]   = rem < TPC ? rem : TPC;
            }
        }
    }
    if (b == 0 && t == 127) g_numWork = s_scan[127] >> 16;
    __syncthreads();
    int id = myseg + t;
    int pos = atomicAdd(&h_pre[cat[id]], 1);
    g_perm[pos] = id;
}

// ---------------- tensor-core MLP via mma.sync (HMMA), 512 threads ----------------
// One CTA = (category, 128-token tile). bf16 hi/lo 3-term MMAs, fp32 accum.
// 16 warps: wm = warp>>2 (32-row m-tile), wn = warp&3.
// Layer 1: warp = 32x32; layer 2: warp = 32x16.
// RACE FIX vs R15/R16: barrier after layer-1 k-loop, then h goes into the
// DEAD B1 buffer (not over A). No in-place overwrite of data still being read.
__global__ void __launch_bounds__(512, 1)
k_mlp(const float* __restrict__ x,
      const float* __restrict__ W1, const float* __restrict__ b1,
      const float* __restrict__ W2, const float* __restrict__ b2,
      float* __restrict__ out) {
    extern __shared__ char smem[];
    char* smA_hi  = smem + SM_A_HI;
    char* smA_lo  = smem + SM_A_LO;
    char* smH_hi  = smem + SM_H_HI;    // B1 in phase 1, h in phase 2
    char* smH_lo  = smem + SM_H_LO;
    char* smB2_hi = smem + SM_B2_HI;
    char* smB2_lo = smem + SM_B2_LO;

    int w = blockIdx.x;
    if (w >= g_numWork) return;
    int c = g_workCat[w], start = g_workStart[w], cnt = g_workCnt[w];
    int tid = threadIdx.x, warp = tid >> 5, lane = tid & 31;

    // ---- stage A = x rows (bf16 hi/lo), rows m = token index in chunk ----
    #pragma unroll 2
    for (int i = tid; i < TPC * 32; i += 512) {
        int m = i >> 5, q = i & 31;       // q = float4 index (k = 4q)
        int tk = (m < cnt) ? g_perm[start + m] : -1;
        float4 v = (tk >= 0) ? __ldg((const float4*)(x + (size_t)tk * Dd) + q)
                             : make_float4(0.f, 0.f, 0.f, 0.f);
        uint32_t h0, l0, h1, l1;
        split2(v.x, v.y, h0, l0);
        split2(v.z, v.w, h1, l1);
        uint32_t off = (uint32_t)m * KSB + (uint32_t)q * 8;
        *(uint2*)(smA_hi + off) = make_uint2(h0, h1);
        *(uint2*)(smA_lo + off) = make_uint2(l0, l1);
    }

    // ---- stage B1 = W1^T into the H buffer: rows n = H col, k = D pairs ----
    {
        const float* W1c = W1 + (size_t)c * Dd * Hh;
        #pragma unroll 4
        for (int i = tid; i < (Dd / 2) * Hh; i += 512) {
            int d2 = i >> 7, h = i & 127;
            const float* p = W1c + (size_t)(2 * d2) * Hh + h;
            float v0 = __ldg(p), v1 = __ldg(p + Hh);
            uint32_t hp, lp;
            split2(v0, v1, hp, lp);
            uint32_t off = (uint32_t)h * KSB + (uint32_t)d2 * 4;
            *(uint32_t*)(smH_hi + off) = hp;
            *(uint32_t*)(smH_lo + off) = lp;
        }
    }

    // ---- stage B2 = W2^T upfront: rows n = O col, k = H pairs ----
    {
        const float* W2c = W2 + (size_t)c * Hh * Oo;
        #pragma unroll 2
        for (int i = tid; i < (Hh / 2) * Oo; i += 512) {
            int k2 = i >> 6, o = i & 63;
            const float* p = W2c + (size_t)(2 * k2) * Oo + o;
            float v0 = __ldg(p), v1 = __ldg(p + Oo);
            uint32_t hp, lp;
            split2(v0, v1, hp, lp);
            uint32_t off = (uint32_t)o * KSB + (uint32_t)k2 * 4;
            *(uint32_t*)(smB2_hi + off) = hp;
            *(uint32_t*)(smB2_lo + off) = lp;
        }
    }
    __syncthreads();

    int wm = warp >> 2, wn = warp & 3;
    int g = lane >> 2, tg = lane & 3;
    int mb = wm * 32;

    // ================= layer 1: warp = 32 rows x 32 cols =================
    float acc[2][4][4];
    #pragma unroll
    for (int mt = 0; mt < 2; mt++)
        #pragma unroll
        for (int nt = 0; nt < 4; nt++)
            #pragma unroll
            for (int j = 0; j < 4; j++) acc[mt][nt][j] = 0.f;

    {
        int nb = wn * 32;
        #pragma unroll 1
        for (int kt = 0; kt < 8; kt++) {
            uint32_t kb = (uint32_t)kt * 32 + (uint32_t)tg * 4;
            uint32_t aHi[2][4], aLo[2][4];
            #pragma unroll
            for (int mt = 0; mt < 2; mt++) {
                uint32_t base = (uint32_t)(mb + mt * 16 + g) * KSB + kb;
                aHi[mt][0] = *(uint32_t*)(smA_hi + base);
                aHi[mt][1] = *(uint32_t*)(smA_hi + base + 8 * KSB);
                aHi[mt][2] = *(uint32_t*)(smA_hi + base + 16);
                aHi[mt][3] = *(uint32_t*)(smA_hi + base + 8 * KSB + 16);
                aLo[mt][0] = *(uint32_t*)(smA_lo + base);
                aLo[mt][1] = *(uint32_t*)(smA_lo + base + 8 * KSB);
                aLo[mt][2] = *(uint32_t*)(smA_lo + base + 16);
                aLo[mt][3] = *(uint32_t*)(smA_lo + base + 8 * KSB + 16);
            }
            #pragma unroll
            for (int nt = 0; nt < 4; nt++) {
                uint32_t bbase = (uint32_t)(nb + nt * 8 + g) * KSB + kb;
                uint32_t bHi[2], bLo[2];
                bHi[0] = *(uint32_t*)(smH_hi + bbase);
                bHi[1] = *(uint32_t*)(smH_hi + bbase + 16);
                bLo[0] = *(uint32_t*)(smH_lo + bbase);
                bLo[1] = *(uint32_t*)(smH_lo + bbase + 16);
                #pragma unroll
                for (int mt = 0; mt < 2; mt++) {
                    MMA16816(acc[mt][nt], aHi[mt], bHi);
                    MMA16816(acc[mt][nt], aLo[mt], bHi);
                    MMA16816(acc[mt][nt], aHi[mt], bLo);
                }
            }
        }
    }

    __syncthreads();   // ALL warps done reading A and B1 (acc lives in regs)

    // ---- epilogue 1: h = relu(D1 + b1) -> bf16 hi/lo into the (dead) B1 buffer ----
    {
        int nb = wn * 32;
        const float* b1c = b1 + (size_t)c * Hh;
        #pragma unroll
        for (int nt = 0; nt < 4; nt++) {
            int col = nb + nt * 8 + tg * 2;
            float bc0 = __ldg(b1c + col), bc1 = __ldg(b1c + col + 1);
            #pragma unroll
            for (int mt = 0; mt < 2; mt++) {
                int r0 = mb + mt * 16 + g;
                float v00 = fmaxf(acc[mt][nt][0] + bc0, 0.f);
                float v01 = fmaxf(acc[mt][nt][1] + bc1, 0.f);
                float v10 = fmaxf(acc[mt][nt][2] + bc0, 0.f);
                float v11 = fmaxf(acc[mt][nt][3] + bc1, 0.f);
                uint32_t hp0, lp0, hp1, lp1;
                split2(v00, v01, hp0, lp0);
                split2(v10, v11, hp1, lp1);
                uint32_t o0 = (uint32_t)r0 * KSB + (uint32_t)col * 2;
                uint32_t o1 = (uint32_t)(r0 + 8) * KSB + (uint32_t)col * 2;
                *(uint32_t*)(smH_hi + o0) = hp0;
                *(uint32_t*)(smH_lo + o0) = lp0;
                *(uint32_t*)(smH_hi + o1) = hp1;
                *(uint32_t*)(smH_lo + o1) = lp1;
            }
        }
    }
    __syncthreads();   // h complete and visible

    // ================= layer 2: warp = 32 rows x 16 cols =================
    float acc2[2][2][4];
    #pragma unroll
    for (int mt = 0; mt < 2; mt++)
        #pragma unroll
        for (int nt = 0; nt < 2; nt++)
            #pragma unroll
            for (int j = 0; j < 4; j++) acc2[mt][nt][j] = 0.f;

    {
        int nb2 = wn * 16;
        #pragma unroll 1
        for (int kt = 0; kt < 8; kt++) {
            uint32_t kb = (uint32_t)kt * 32 + (uint32_t)tg * 4;
            uint32_t aHi[2][4], aLo[2][4];
            #pragma unroll
            for (int mt = 0; mt < 2; mt++) {
                uint32_t base = (uint32_t)(mb + mt * 16 + g) * KSB + kb;
                aHi[mt][0] = *(uint32_t*)(smH_hi + base);
                aHi[mt][1] = *(uint32_t*)(smH_hi + base + 8 * KSB);
                aHi[mt][2] = *(uint32_t*)(smH_hi + base + 16);
                aHi[mt][3] = *(uint32_t*)(smH_hi + base + 8 * KSB + 16);
                aLo[mt][0] = *(uint32_t*)(smH_lo + base);
                aLo[mt][1] = *(uint32_t*)(smH_lo + base + 8 * KSB);
                aLo[mt][2] = *(uint32_t*)(smH_lo + base + 16);
                aLo[mt][3] = *(uint32_t*)(smH_lo + base + 8 * KSB + 16);
            }
            #pragma unroll
            for (int nt = 0; nt < 2; nt++) {
                uint32_t bbase = (uint32_t)(nb2 + nt * 8 + g) * KSB + kb;
                uint32_t bHi[2], bLo[2];
                bHi[0] = *(uint32_t*)(smB2_hi + bbase);
                bHi[1] = *(uint32_t*)(smB2_hi + bbase + 16);
                bLo[0] = *(uint32_t*)(smB2_lo + bbase);
                bLo[1] = *(uint32_t*)(smB2_lo + bbase + 16);
                #pragma unroll
                for (int mt = 0; mt < 2; mt++) {
                    MMA16816(acc2[mt][nt], aHi[mt], bHi);
                    MMA16816(acc2[mt][nt], aLo[mt], bHi);
                    MMA16816(acc2[mt][nt], aHi[mt], bLo);
                }
            }
        }

        // ---- out = D2 + b2 ----
        const float* b2c = b2 + (size_t)c * Oo;
        #pragma unroll
        for (int nt = 0; nt < 2; nt++) {
            int col = nb2 + nt * 8 + tg * 2;
            float bc0 = __ldg(b2c + col), bc1 = __ldg(b2c + col + 1);
            #pragma unroll
            for (int mt = 0; mt < 2; mt++) {
                int r0 = mb + mt * 16 + g;
                if (r0 < cnt) {
                    int tk = g_perm[start + r0];
                    float2 o;
                    o.x = acc2[mt][nt][0] + bc0;
                    o.y = acc2[mt][nt][1] + bc1;
                    *(float2*)(out + (size_t)tk * Oo + col) = o;
                }
                int r1 = r0 + 8;
                if (r1 < cnt) {
                    int tk = g_perm[start + r1];
                    float2 o;
                    o.x = acc2[mt][nt][2] + bc0;
                    o.y = acc2[mt][nt][3] + bc1;
                    *(float2*)(out + (size_t)tk * Oo + col) = o;
                }
            }
        }
    }
}

extern "C" void kernel_launch(void* const* d_in, const int* in_sizes, int n_in,
                              void* d_out, int out_size) {
    const float* x   = (const float*)d_in[0];
    const int*   cat = (const int*)  d_in[1];
    const float* W1  = (const float*)d_in[2];
    const float* b1  = (const float*)d_in[3];
    const float* W2  = (const float*)d_in[4];
    const float* b2  = (const float*)d_in[5];
    float* out = (float*)d_out;

    static bool attr_set = false;
    if (!attr_set) {
        cudaFuncSetAttribute(k_mlp, cudaFuncAttributeMaxDynamicSharedMemorySize, SMEM_TOTAL);
        attr_set = true;
    }

    k_sort<<<NB, BT>>>(cat);
    k_mlp<<<MAXW, 512, SMEM_TOTAL>>>(x, W1, b1, W2, b2, out);
}